// round 10
// baseline (speedup 1.0000x reference)
#include <cuda_runtime.h>

#define HEPS 1e-8f
#define HMAX_NORM 20.0f

// 256-bit global load/store (Blackwell sm_100+). ptr must be 32B-aligned.
// volatile: prevents CSE so the epilogue re-load is really emitted.
__device__ __forceinline__ void ldg256(const float* __restrict__ p, float* r) {
    asm volatile("ld.global.v8.b32 {%0,%1,%2,%3,%4,%5,%6,%7}, [%8];"
        : "=r"(((unsigned*)r)[0]), "=r"(((unsigned*)r)[1]),
          "=r"(((unsigned*)r)[2]), "=r"(((unsigned*)r)[3]),
          "=r"(((unsigned*)r)[4]), "=r"(((unsigned*)r)[5]),
          "=r"(((unsigned*)r)[6]), "=r"(((unsigned*)r)[7])
        : "l"(p));
}
__device__ __forceinline__ void stg256(float* __restrict__ p, const float* r) {
    asm volatile("st.global.v8.b32 [%8], {%0,%1,%2,%3,%4,%5,%6,%7};"
        :: "r"(((const unsigned*)r)[0]), "r"(((const unsigned*)r)[1]),
           "r"(((const unsigned*)r)[2]), "r"(((const unsigned*)r)[3]),
           "r"(((const unsigned*)r)[4]), "r"(((const unsigned*)r)[5]),
           "r"(((const unsigned*)r)[6]), "r"(((const unsigned*)r)[7]),
           "l"(p) : "memory");
}

__global__ void __launch_bounds__(256, 8)
hyperbolic_expmap_kernel(const float* __restrict__ x,
                         const float* __restrict__ v,
                         float* __restrict__ out,
                         int nrows)
{
    int tid = blockIdx.x * blockDim.x + threadIdx.x;
    int row = tid >> 2;        // 4 threads per row, each owns 8 contiguous floats
    int sub = tid & 3;
    if (row >= nrows) return;
    const bool lead = (sub == 0);   // owns the time coordinate (element 0)

    long off = (long)row * 32 + sub * 8;   // 32B-aligned lane offset

    // ---- phase 1: load + fused reduction (registers die after this) ----
    float s = 0.f, xv = 0.f, vvm = 0.f;
    float v0own = 0.f;
    {
        float xr[8], vr[8];
        ldg256(x + off, xr);
        ldg256(v + off, vr);
        v0own = vr[0];
#pragma unroll
        for (int i = 0; i < 8; i++) {
            float xi = xr[i], vi = vr[i];
            float sq = xi * xi;
            float p  = xi * vi;
            float q  = vi * vi;
            if (lead && i == 0) { sq = 0.f; p = 0.f; q = -q; }
            s += sq; xv += p; vvm += q;
        }
    }
#pragma unroll
    for (int m = 1; m <= 2; m <<= 1) {
        s   += __shfl_xor_sync(0xffffffffu, s,   m);
        xv  += __shfl_xor_sync(0xffffffffu, xv,  m);
        vvm += __shfl_xor_sync(0xffffffffu, vvm, m);
    }
    float v0 = __shfl_sync(0xffffffffu, v0own, 0, 4);  // time comp of v

    // ---- group-uniform scalar math ----
    bool  tiny  = (s < HEPS);
    float t     = sqrtf(1.f + (tiny ? HEPS : s));   // projected time coord
    float scale = tiny ? 0.f : 1.f;
    float inner = fmaf(-t, v0, scale * xv);         // <x_proj, v>_M
    float vv    = fmaf(inner, inner, vvm);          // <v_proj, v_proj>_M

    float a  = fabsf(vv);
    float vn = (a < HEPS) ? (sqrtf(a) * 0.5f) : sqrtf(a);
    vn = fminf(vn, HMAX_NORM);
    float c1, c2;
    if (vn < HEPS) { c1 = 1.f; c2 = 0.f; }
    else {
        float e  = __expf(vn);
        float ei = __expf(-vn);
        c1 = 0.5f * (e + ei);
        c2 = (0.5f * (e - ei)) / fmaxf(vn, HEPS);
    }

    // result = A*x_p + c2*v,  A = c1 + c2*inner ; fold final projection
    float A  = fmaf(c2, inner, c1);
    float r0 = fmaf(A, t, c2 * v0);                 // result time coord
    float s2 = fmaf(c2 * c2, vv, fmaf(r0, r0, -c1 * c1));
    bool  tiny2 = (s2 < HEPS);
    float t2  = sqrtf(1.f + (tiny2 ? HEPS : s2));
    float sc2 = tiny2 ? 0.f : 1.f;

    float C1 = sc2 * (A * scale);   // coefficient on x (space components)
    float C2 = sc2 * c2;            // coefficient on v

    // ---- phase 2: re-load (L1/L2 hit), combine, store ----
    {
        float xr[8], vr[8], r[8];
        ldg256(x + off, xr);
        ldg256(v + off, vr);
#pragma unroll
        for (int i = 0; i < 8; i++) r[i] = fmaf(C1, xr[i], C2 * vr[i]);
        if (lead) r[0] = t2;
        stg256(out + off, r);
    }
}

extern "C" void kernel_launch(void* const* d_in, const int* in_sizes, int n_in,
                              void* d_out, int out_size) {
    const float* x = (const float*)d_in[0];
    const float* v = (const float*)d_in[1];
    float* out = (float*)d_out;
    int nrows = in_sizes[0] / 32;
    const int threads = 256;
    long total = (long)nrows * 4;
    int blocks = (int)((total + threads - 1) / threads);
    hyperbolic_expmap_kernel<<<blocks, threads>>>(x, v, out, nrows);
}

// round 11
// speedup vs baseline: 1.0428x; 1.0428x over previous
#include <cuda_runtime.h>

#define HEPS 1e-8f
#define HMAX_NORM 20.0f

// 256-bit global accesses (Blackwell sm_100+). ptr must be 32B-aligned.
// Loads: read-only path, no L1 allocation (zero-reuse streaming workload).
__device__ __forceinline__ void ldg256_nc(const float* __restrict__ p, float* r) {
    asm volatile("ld.global.nc.L1::no_allocate.v8.b32 {%0,%1,%2,%3,%4,%5,%6,%7}, [%8];"
        : "=r"(((unsigned*)r)[0]), "=r"(((unsigned*)r)[1]),
          "=r"(((unsigned*)r)[2]), "=r"(((unsigned*)r)[3]),
          "=r"(((unsigned*)r)[4]), "=r"(((unsigned*)r)[5]),
          "=r"(((unsigned*)r)[6]), "=r"(((unsigned*)r)[7])
        : "l"(p));
}
// Stores: evict-first streaming.
__device__ __forceinline__ void stg256_cs(float* __restrict__ p, const float* r) {
    asm volatile("st.global.cs.v8.b32 [%8], {%0,%1,%2,%3,%4,%5,%6,%7};"
        :: "r"(((const unsigned*)r)[0]), "r"(((const unsigned*)r)[1]),
           "r"(((const unsigned*)r)[2]), "r"(((const unsigned*)r)[3]),
           "r"(((const unsigned*)r)[4]), "r"(((const unsigned*)r)[5]),
           "r"(((const unsigned*)r)[6]), "r"(((const unsigned*)r)[7]),
           "l"(p) : "memory");
}

__global__ void __launch_bounds__(256)
hyperbolic_expmap_kernel(const float* __restrict__ x,
                         const float* __restrict__ v,
                         float* __restrict__ out,
                         int nrows)
{
    int tid = blockIdx.x * blockDim.x + threadIdx.x;
    int row = tid >> 2;        // 4 threads per row, each owns 8 contiguous floats
    int sub = tid & 3;
    if (row >= nrows) return;
    const bool lead = (sub == 0);   // owns the time coordinate (element 0)

    long off = (long)row * 32 + sub * 8;   // 32B-aligned lane offset

    // Two 256-bit loads cover this lane's x and v data (kept live in regs)
    float xr[8], vr[8];
    ldg256_nc(x + off, xr);
    ldg256_nc(v + off, vr);

    // ---- single fused reduction pass over ORIGINAL data ----
    // s = sum_space x_i^2 ; xv = sum_space x_i v_i ; vvm = <v,v>_Minkowski
    float s = 0.f, xv = 0.f, vvm = 0.f;
#pragma unroll
    for (int i = 0; i < 8; i++) {
        float xi = xr[i], vi = vr[i];
        float sq = xi * xi;
        float p  = xi * vi;
        float q  = vi * vi;
        if (lead && i == 0) { sq = 0.f; p = 0.f; q = -q; }
        s += sq; xv += p; vvm += q;
    }
#pragma unroll
    for (int m = 1; m <= 2; m <<= 1) {
        s   += __shfl_xor_sync(0xffffffffu, s,   m);
        xv  += __shfl_xor_sync(0xffffffffu, xv,  m);
        vvm += __shfl_xor_sync(0xffffffffu, vvm, m);
    }
    float v0 = __shfl_sync(0xffffffffu, vr[0], 0, 4);  // time comp of v

    // ---- group-uniform scalar math ----
    bool  tiny  = (s < HEPS);
    float t     = sqrtf(1.f + (tiny ? HEPS : s));   // projected time coord
    float scale = tiny ? 0.f : 1.f;
    float inner = fmaf(-t, v0, scale * xv);         // <x_proj, v>_M
    float vv    = fmaf(inner, inner, vvm);          // <v_proj, v_proj>_M

    float a  = fabsf(vv);
    float vn = (a < HEPS) ? (sqrtf(a) * 0.5f) : sqrtf(a);
    vn = fminf(vn, HMAX_NORM);
    float c1, c2;
    if (vn < HEPS) { c1 = 1.f; c2 = 0.f; }
    else {
        float e  = __expf(vn);
        float ei = __expf(-vn);
        c1 = 0.5f * (e + ei);
        c2 = (0.5f * (e - ei)) / fmaxf(vn, HEPS);
    }

    // result = c1*x_p + c2*(v + inner*x_p) = A*x_p + c2*v,  A = c1 + c2*inner
    float A  = fmaf(c2, inner, c1);
    float r0 = fmaf(A, t, c2 * v0);                 // result time coord
    // final projection: s2 = c2^2*vv + r0^2 - c1^2
    float s2 = fmaf(c2 * c2, vv, fmaf(r0, r0, -c1 * c1));
    bool  tiny2 = (s2 < HEPS);
    float t2  = sqrtf(1.f + (tiny2 ? HEPS : s2));
    float sc2 = tiny2 ? 0.f : 1.f;

    // fold everything into one linear combination of the ORIGINAL loads
    float C1 = sc2 * (A * scale);   // coefficient on x (space components)
    float C2 = sc2 * c2;            // coefficient on v

    float r[8];
#pragma unroll
    for (int i = 0; i < 8; i++) r[i] = fmaf(C1, xr[i], C2 * vr[i]);
    if (lead) r[0] = t2;

    stg256_cs(out + off, r);
}

extern "C" void kernel_launch(void* const* d_in, const int* in_sizes, int n_in,
                              void* d_out, int out_size) {
    const float* x = (const float*)d_in[0];
    const float* v = (const float*)d_in[1];
    float* out = (float*)d_out;
    int nrows = in_sizes[0] / 32;
    const int threads = 256;
    long total = (long)nrows * 4;
    int blocks = (int)((total + threads - 1) / threads);
    hyperbolic_expmap_kernel<<<blocks, threads>>>(x, v, out, nrows);
}

// round 16
// speedup vs baseline: 1.0519x; 1.0086x over previous
#include <cuda_runtime.h>

#define HEPS 1e-8f
#define HMAX_NORM 20.0f

// 256-bit global accesses (Blackwell sm_100+). ptr must be 32B-aligned.
// Non-volatile: let ptxas schedule/batch freely. .nc = read-only data path.
__device__ __forceinline__ void ldg256_nc(const float* __restrict__ p, float* r) {
    asm("ld.global.nc.v8.b32 {%0,%1,%2,%3,%4,%5,%6,%7}, [%8];"
        : "=r"(((unsigned*)r)[0]), "=r"(((unsigned*)r)[1]),
          "=r"(((unsigned*)r)[2]), "=r"(((unsigned*)r)[3]),
          "=r"(((unsigned*)r)[4]), "=r"(((unsigned*)r)[5]),
          "=r"(((unsigned*)r)[6]), "=r"(((unsigned*)r)[7])
        : "l"(p));
}
__device__ __forceinline__ void stg256(float* __restrict__ p, const float* r) {
    asm volatile("st.global.v8.b32 [%8], {%0,%1,%2,%3,%4,%5,%6,%7};"
        :: "r"(((const unsigned*)r)[0]), "r"(((const unsigned*)r)[1]),
           "r"(((const unsigned*)r)[2]), "r"(((const unsigned*)r)[3]),
           "r"(((const unsigned*)r)[4]), "r"(((const unsigned*)r)[5]),
           "r"(((const unsigned*)r)[6]), "r"(((const unsigned*)r)[7]),
           "l"(p) : "memory");
}

__global__ void __launch_bounds__(256)
hyperbolic_expmap_kernel(const float* __restrict__ x,
                         const float* __restrict__ v,
                         float* __restrict__ out,
                         int nrows)
{
    int tid = blockIdx.x * blockDim.x + threadIdx.x;
    int row = tid >> 2;        // 4 threads per row, each owns 8 contiguous floats
    int sub = tid & 3;
    if (row >= nrows) return;
    const bool lead = (sub == 0);   // owns the time coordinate (element 0)

    long off = (long)row * 32 + sub * 8;   // 32B-aligned lane offset

    // Two 256-bit loads cover this lane's x and v data (kept live in regs)
    float xr[8], vr[8];
    ldg256_nc(x + off, xr);
    ldg256_nc(v + off, vr);

    // ---- single fused reduction pass over ORIGINAL data ----
    // s = sum_space x_i^2 ; xv = sum_space x_i v_i ; vvm = <v,v>_Minkowski
    float s = 0.f, xv = 0.f, vvm = 0.f;
#pragma unroll
    for (int i = 0; i < 8; i++) {
        float xi = xr[i], vi = vr[i];
        float sq = xi * xi;
        float p  = xi * vi;
        float q  = vi * vi;
        if (lead && i == 0) { sq = 0.f; p = 0.f; q = -q; }
        s += sq; xv += p; vvm += q;
    }
#pragma unroll
    for (int m = 1; m <= 2; m <<= 1) {
        s   += __shfl_xor_sync(0xffffffffu, s,   m);
        xv  += __shfl_xor_sync(0xffffffffu, xv,  m);
        vvm += __shfl_xor_sync(0xffffffffu, vvm, m);
    }
    float v0 = __shfl_sync(0xffffffffu, vr[0], 0, 4);  // time comp of v

    // ---- group-uniform scalar math ----
    bool  tiny  = (s < HEPS);
    float t     = sqrtf(1.f + (tiny ? HEPS : s));   // projected time coord
    float scale = tiny ? 0.f : 1.f;
    float inner = fmaf(-t, v0, scale * xv);         // <x_proj, v>_M
    float vv    = fmaf(inner, inner, vvm);          // <v_proj, v_proj>_M

    float a  = fabsf(vv);
    float vn = (a < HEPS) ? (sqrtf(a) * 0.5f) : sqrtf(a);
    vn = fminf(vn, HMAX_NORM);
    float c1, c2;
    if (vn < HEPS) { c1 = 1.f; c2 = 0.f; }
    else {
        float e  = __expf(vn);
        float ei = __expf(-vn);
        c1 = 0.5f * (e + ei);
        c2 = (0.5f * (e - ei)) / fmaxf(vn, HEPS);
    }

    // result = c1*x_p + c2*(v + inner*x_p) = A*x_p + c2*v,  A = c1 + c2*inner
    float A  = fmaf(c2, inner, c1);
    float r0 = fmaf(A, t, c2 * v0);                 // result time coord
    // final projection: s2 = c2^2*vv + r0^2 - c1^2
    float s2 = fmaf(c2 * c2, vv, fmaf(r0, r0, -c1 * c1));
    bool  tiny2 = (s2 < HEPS);
    float t2  = sqrtf(1.f + (tiny2 ? HEPS : s2));
    float sc2 = tiny2 ? 0.f : 1.f;

    // fold everything into one linear combination of the ORIGINAL loads
    float C1 = sc2 * (A * scale);   // coefficient on x (space components)
    float C2 = sc2 * c2;            // coefficient on v

    float r[8];
#pragma unroll
    for (int i = 0; i < 8; i++) r[i] = fmaf(C1, xr[i], C2 * vr[i]);
    if (lead) r[0] = t2;

    stg256(out + off, r);
}

extern "C" void kernel_launch(void* const* d_in, const int* in_sizes, int n_in,
                              void* d_out, int out_size) {
    const float* x = (const float*)d_in[0];
    const float* v = (const float*)d_in[1];
    float* out = (float*)d_out;
    int nrows = in_sizes[0] / 32;
    const int threads = 256;
    long total = (long)nrows * 4;
    int blocks = (int)((total + threads - 1) / threads);
    hyperbolic_expmap_kernel<<<blocks, threads>>>(x, v, out, nrows);
}